// round 16
// baseline (speedup 1.0000x reference)
#include <cuda_runtime.h>
#include <math.h>
#include <stdint.h>

// ---------------------------------------------------------------------------
// CoDAConv2d rewritten (single fused kernel, WARP-AUTONOMOUS tasks):
//   act_o  = sum_c x_c * (A_o^T nb)_c + nb.b_o
//   norm_o = sqrt(x^T G_o x + 2 u_o^T x + s_o) + eps
// Warp-task = (16px chunk, o-group of 4). Warp wid owns og=wid permanently
// (F table loaded once). Per-warp double-buffered tile filled by cp.async
// with zero-fill; NO __syncthreads in the main loop — warp-local
// cp.async.wait_group + __syncwarp only. Compute core identical to R15:
// fused 10-col x 3-row half-sweeps (software-pipelined LDS), 16-value/8-lane
// butterfly, rsqrt epilogue. Block-0 fused prep with spin.
// ---------------------------------------------------------------------------

#define B_  4
#define CI  8
#define CO  16
#define HH  112
#define WW  112
#define PATCH 72

#define CHUNK 16
#define COLS  (CHUNK + 2)               // 18
#define TILE_ELEMS (3 * COLS * 8)       // 432
#define NCHUNK (WW / CHUNK)             // 7
#define NTASK_OG (B_ * HH * NCHUNK)     // 3136 chunk-tasks per o-group
#define GRID   444                      // 148 SMs * 3 blocks (all resident)

typedef unsigned long long ull;

// packed-pair tables (index t16 = o*8+c)
__device__ ull   gF2[36 * 128];
__device__ float gZ[9 * 128];
__device__ ull   gQ2[4 * 128];
__device__ float gU[128];
__device__ float gS[128];
__device__ int   gCtr4[4] = {0, 0, 0, 0};
__device__ int   gDone = 0;
__device__ int   gFlag = 0;

// --- f32x2 helpers -----------------------------------------------------------
__device__ __forceinline__ ull ffma2(ull a, ull b, ull c) {
    ull d; asm("fma.rn.f32x2 %0, %1, %2, %3;" : "=l"(d) : "l"(a), "l"(b), "l"(c));
    return d;
}
__device__ __forceinline__ ull fadd2(ull a, ull b) {
    ull d; asm("add.rn.f32x2 %0, %1, %2;" : "=l"(d) : "l"(a), "l"(b));
    return d;
}
__device__ __forceinline__ ull pack2(float lo, float hi) {
    ull d; asm("mov.b64 %0, {%1, %2};" : "=l"(d) : "f"(lo), "f"(hi));
    return d;
}
__device__ __forceinline__ float hsum2(ull a) {
    float lo, hi; asm("mov.b64 {%0, %1}, %2;" : "=f"(lo), "=f"(hi) : "l"(a));
    return lo + hi;
}
__device__ __forceinline__ uint32_t smem_u32(const void* p) {
    uint32_t a;
    asm("{ .reg .u64 t; cvta.to.shared.u64 t, %1; cvt.u32.u64 %0, t; }"
        : "=r"(a) : "l"(p));
    return a;
}

// --- per-warp tile fill via cp.async (zero-fill on OOB) -----------------------
__device__ __forceinline__ void issue_tile(const float* __restrict__ in,
                                           int task, int lane, uint32_t sbase) {
    const int rowid = task / NCHUNK;
    const int cw    = (task % NCHUNK) * CHUNK;
    const int b     = rowid / HH;
    const int h     = rowid % HH;
    #pragma unroll
    for (int k = 0; k < 14; k++) {
        const int idx = lane + k * 32;
        if (idx < TILE_ELEMS) {                 // k==13: lanes < 16
            const int ch   = idx & 7;
            const int rest = idx >> 3;
            const int col  = rest % COLS;
            const int r    = rest / COLS;
            const int ir   = h - 1 + r;
            const int ic   = cw - 1 + col;
            const bool ok  = ((unsigned)ir < (unsigned)HH) &&
                             ((unsigned)ic < (unsigned)WW);
            const float* src = &in[((b * CI + ch) * HH + ir) * WW + ic];
            const int sz = ok ? 4 : 0;          // src-size 0 => zero-fill
            asm volatile("cp.async.ca.shared.global [%0], [%1], 4, %2;"
                         :: "r"(sbase + idx * 4), "l"(src), "r"(sz) : "memory");
        }
    }
    asm volatile("cp.async.commit_group;" ::: "memory");
}

// --- fused 8-pixel half-sweep: 10 cols x 3 rows, software-pipelined ----------
__device__ __forceinline__ void conv_half(const float tile[3][COLS][8],
                                          int wlb, int c,
                                          const ull* Fp, const float* Zreg,
                                          const ull* Qp, ull qinit, float Qs,
                                          float rv[8], float rq[8]) {
    ull   m[8];
    float z[8], xc[8];
    #pragma unroll
    for (int px = 0; px < 8; px++) { m[px] = 0ull; z[px] = 0.f; }

    const float* pv0 = &tile[0][wlb][0];
    ulonglong2 VA = *(const ulonglong2*)pv0;
    ulonglong2 VB = *((const ulonglong2*)pv0 + 1);
    float      vc = pv0[c];

    #pragma unroll
    for (int it = 0; it < 30; it++) {
        const int dh = it / 10;
        const int k  = it % 10;

        ulonglong2 nVA, nVB;
        float      nvc;
        if (it < 29) {
            const int ndh = (it + 1) / 10;
            const int nk  = (it + 1) % 10;
            const float* pn = &tile[ndh][wlb + nk][0];
            nVA = *(const ulonglong2*)pn;
            nVB = *((const ulonglong2*)pn + 1);
            nvc = pn[c];
        }

        const int pxlo = (k - 2 > 0) ? (k - 2) : 0;
        const int pxhi = (k < 7) ? k : 7;
        #pragma unroll
        for (int px = pxlo; px <= pxhi; px++) {
            const int j = dh * 3 + (k - px);
            m[px] = ffma2(VA.x, Fp[ 0 + j], m[px]);
            m[px] = ffma2(VA.y, Fp[ 9 + j], m[px]);
            m[px] = ffma2(VB.x, Fp[18 + j], m[px]);
            m[px] = ffma2(VB.y, Fp[27 + j], m[px]);
            z[px] = fmaf(vc, Zreg[j], z[px]);
        }
        if (dh == 1 && k >= 1 && k <= 8) {
            const int px = k - 1;
            xc[px] = vc;
            ull qa = ffma2(VA.x, Qp[0], qinit);
            qa = ffma2(VB.x, Qp[2], qa);
            ull qb = ffma2(VA.y, Qp[1], 0ull);
            qb = ffma2(VB.y, Qp[3], qb);
            rq[px] = fmaf(vc, hsum2(fadd2(qa, qb)), Qs);
        }

        if (it < 29) { VA = nVA; VB = nVB; vc = nvc; }
    }

    #pragma unroll
    for (int px = 0; px < 8; px++)
        rv[px] = fmaf(xc[px], hsum2(m[px]), z[px]);
}

// --- main kernel ----------------------------------------------------------------
__global__ __launch_bounds__(128, 3)
void coda_main_kernel(const float* __restrict__ in,
                      const float* __restrict__ w_pred,
                      const float* __restrict__ b_pred,
                      float* __restrict__ out) {
    const int t    = threadIdx.x;
    const int wid  = t >> 5;          // 0..3 == o-group
    const int lane = t & 31;
    const int ol   = lane >> 3;       // 0..3
    const int c    = lane & 7;
    const int o    = wid * 4 + ol;
    const int t16  = o * 8 + c;

    // ===== fused prep: block 0 builds tables (all 128 threads) =============
    if (blockIdx.x == 0) {
        const int po = t >> 3, pc = t & 7;
        #pragma unroll 4
        for (int bx = 0; bx < 36; bx++) {
            const int i = bx / 9, j = bx % 9;
            float lo = w_pred[(((2 * i)     * 9 + j) * 16 + po) * 8 + pc];
            float hi = w_pred[(((2 * i + 1) * 9 + j) * 16 + po) * 8 + pc];
            gF2[bx * 128 + t] = pack2(lo, hi);
            if (bx < 9) gZ[bx * 128 + t] = b_pred[(pc * 9 + bx) * 16 + po];
        }
        float G8[8] = {0.f, 0.f, 0.f, 0.f, 0.f, 0.f, 0.f, 0.f};
        float uacc = 0.f, ssum = 0.f;
        #pragma unroll 4
        for (int p = 0; p < PATCH; p++) {
            const float wc = w_pred[(p * 16 + po) * 8 + pc];
            const float4 k0 = *(const float4*)&w_pred[(p * 16 + po) * 8];
            const float4 k1 = *(const float4*)&w_pred[(p * 16 + po) * 8 + 4];
            const float bv = b_pred[p * 16 + po];
            G8[0] = fmaf(wc, k0.x, G8[0]); G8[1] = fmaf(wc, k0.y, G8[1]);
            G8[2] = fmaf(wc, k0.z, G8[2]); G8[3] = fmaf(wc, k0.w, G8[3]);
            G8[4] = fmaf(wc, k1.x, G8[4]); G8[5] = fmaf(wc, k1.y, G8[5]);
            G8[6] = fmaf(wc, k1.z, G8[6]); G8[7] = fmaf(wc, k1.w, G8[7]);
            uacc = fmaf(wc, bv, uacc);
            ssum = fmaf(bv, bv, ssum);
        }
        #pragma unroll
        for (int kk = 0; kk < 4; kk++)
            gQ2[kk * 128 + t] = pack2(G8[2 * kk], G8[2 * kk + 1]);
        gU[t] = 2.0f * uacc;
        gS[t] = ssum * 0.125f;

        __threadfence();
        __syncthreads();
        if (t == 0) atomicExch(&gFlag, 1);   // release
    }

    // ===== per-warp tile buffers + first task grab (overlaps prep wait) =====
    __shared__ float tiles[4][2][3][COLS][8];
    uint32_t sbase[2];
    sbase[0] = smem_u32(&tiles[wid][0][0][0][0]);
    sbase[1] = smem_u32(&tiles[wid][1][0][0][0]);

    int n;
    if (lane == 0) n = atomicAdd(&gCtr4[wid], 1);
    n = __shfl_sync(0xffffffffu, n, 0);
    if (n < NTASK_OG) issue_tile(in, n, lane, sbase[0]);

    if (blockIdx.x != 0) {
        if (lane == 0) {
            while (atomicAdd(&gFlag, 0) == 0) __nanosleep(64);
        }
        __syncwarp();
        __threadfence();                  // acquire
    }

    // ===== per-thread constant tables =======================================
    ull Fp[36];
    #pragma unroll
    for (int p = 0; p < 36; p++) Fp[p] = gF2[p * 128 + t16];
    float Zreg[9];
    #pragma unroll
    for (int j = 0; j < 9; j++) Zreg[j] = gZ[j * 128 + t16];
    ull Qp[4];
    #pragma unroll
    for (int k = 0; k < 4; k++) Qp[k] = gQ2[k * 128 + t16];
    const ull   qinit = pack2(gU[t16], 0.f);
    const float Qs    = gS[t16];

    // ===== warp-autonomous task loop (no block barriers) =====================
    if (n < NTASK_OG) {
        int buf = 0;
        while (true) {
            int nn;
            if (lane == 0) nn = atomicAdd(&gCtr4[wid], 1);
            nn = __shfl_sync(0xffffffffu, nn, 0);
            if (nn < NTASK_OG) {
                issue_tile(in, nn, lane, sbase[buf ^ 1]);   // prefetch next
                asm volatile("cp.async.wait_group 1;" ::: "memory");
            } else {
                asm volatile("cp.async.wait_group 0;" ::: "memory");
            }
            __syncwarp();

            const int rowid = n / NCHUNK;
            const int cw    = (n % NCHUNK) * CHUNK;
            const int b     = rowid / HH;
            const int h     = rowid % HH;
            float* orow = &out[((b * CO + o) * HH + h) * WW + cw];
            const float (*tile)[COLS][8] =
                (const float (*)[COLS][8])&tiles[wid][buf][0][0][0];

            #pragma unroll
            for (int half = 0; half < 2; half++) {
                const int wlb = half * 8;

                float rv[8], rq[8];
                conv_half(tile, wlb, c, Fp, Zreg, Qp, qinit, Qs, rv, rq);

                // 16-value / 8-lane butterfly: lane c ends with (av, qv), px=c
                const bool h0 = c & 1, h1 = c & 2, h2 = c & 4;
                float sv[4], sq[4];
                #pragma unroll
                for (int i = 0; i < 4; i++) {
                    float gv = h0 ? rv[2 * i] : rv[2 * i + 1];
                    float gq = h0 ? rq[2 * i] : rq[2 * i + 1];
                    float dv = __shfl_xor_sync(0xffffffffu, gv, 1);
                    float dq = __shfl_xor_sync(0xffffffffu, gq, 1);
                    sv[i] = (h0 ? rv[2 * i + 1] : rv[2 * i]) + dv;
                    sq[i] = (h0 ? rq[2 * i + 1] : rq[2 * i]) + dq;
                }
                float uv[2], uq[2];
                #pragma unroll
                for (int i = 0; i < 2; i++) {
                    float gv = h1 ? sv[2 * i] : sv[2 * i + 1];
                    float gq = h1 ? sq[2 * i] : sq[2 * i + 1];
                    float dv = __shfl_xor_sync(0xffffffffu, gv, 2);
                    float dq = __shfl_xor_sync(0xffffffffu, gq, 2);
                    uv[i] = (h1 ? sv[2 * i + 1] : sv[2 * i]) + dv;
                    uq[i] = (h1 ? sq[2 * i + 1] : sq[2 * i]) + dq;
                }
                {
                    float gv = h2 ? uv[0] : uv[1];
                    float gq = h2 ? uq[0] : uq[1];
                    float dv = __shfl_xor_sync(0xffffffffu, gv, 4);
                    float dq = __shfl_xor_sync(0xffffffffu, gq, 4);
                    float av = (h2 ? uv[1] : uv[0]) + dv;    // px = c
                    float qv = (h2 ? uq[1] : uq[0]) + dq;
                    // reference denom = sqrt(qv)+1e-6; qv bounded away from 0,
                    // so av * rsqrt(qv) is within ~1e-5 relative of it.
                    qv = fmaxf(qv, 1e-20f);
                    orow[wlb + c] = av * rsqrtf(qv);         // all 32 lanes
                }
            }

            __syncwarp();       // readers done before this buffer is refilled
            if (nn >= NTASK_OG) break;
            n = nn;
            buf ^= 1;
        }
    }

    // ---- reset for next graph replay: last block out resets everything ----
    __syncthreads();
    if (t == 0) {
        int old = atomicAdd(&gDone, 1);
        if (old == (int)gridDim.x - 1) {
            atomicExch(&gCtr4[0], 0);
            atomicExch(&gCtr4[1], 0);
            atomicExch(&gCtr4[2], 0);
            atomicExch(&gCtr4[3], 0);
            atomicExch(&gFlag, 0);
            atomicExch(&gDone, 0);
        }
    }
}

// ---------------------------------------------------------------------------
extern "C" void kernel_launch(void* const* d_in, const int* in_sizes, int n_in,
                              void* d_out, int out_size) {
    const float* in_tensor = (const float*)d_in[0];
    const float* w_pred    = (const float*)d_in[1];
    const float* b_pred    = (const float*)d_in[2];
    float* out = (float*)d_out;

    coda_main_kernel<<<GRID, 128>>>(in_tensor, w_pred, b_pred, out);
}